// round 14
// baseline (speedup 1.0000x reference)
#include <cuda_runtime.h>
#include <math.h>

#define NPIX 512
#define PARTS 8
#define MAXPARTS 16
#define NCOPY 4
#define SLICES 2
#define CTA 512
#define PF 4                 /* prefetch depth: covers all observed boxes */
#define INF_F 1000000000.0f
#define INF_U 0x4E6E6B28u   /* __float_as_uint(1e9f) */
#define MU_F 1e-8f
#define THRESH 0.05f

// fast approx sqrt: MUFU.RSQ + multiply (d2 == 0 yields NaN -> caller's
// dist<=r test fails, dropping the pixel; exact-center hit is measure-zero)
__device__ __forceinline__ float fsqrt_approx(float x) { return x * rsqrtf(x); }

// Grid (SLICES, B) with cluster (SLICES,1,1). Bbox tiled by 4-aligned float4
// groups with an exact Wg-wide flattened mapping. ALL of a thread's loop
// iterations (<=PF in every observed case; stride is 1024 so the count is a
// shift) issue their LDG.128 back-to-back up front -> one exposed memory
// round instead of one per iteration. MUFU sqrt/div; plain atomicMin into
// NCOPY replicated shared bin words. Cross-CTA reduce via DSMEM atomics +
// cluster barriers; leader formats output from local smem. No global scratch.
__global__ __launch_bounds__(CTA) __cluster_dims__(SLICES, 1, 1)
void pcl_kernel(
    const float* __restrict__ seg_maps,   // (B, N, N)
    const float* __restrict__ paras,      // (B, 4): wx, wy, bx, by
    const float* __restrict__ traj,       // (B, 8, 2)
    const float* __restrict__ cpos,       // (B, 1, 2)
    float* __restrict__ out)              // (B, 16, 3)
{
    const int b   = blockIdx.y;
    const int s   = blockIdx.x;           // cluster rank
    const int tid = threadIdx.x;
    const int cpy = (tid & 3) * PARTS;    // replica select

    __shared__ unsigned smin[NCOPY * PARTS];
    if (tid < NCOPY * PARTS) smin[tid] = INF_U;

    // vectorized scalar params: 4 independent loads, one memory round
    const float4 pp = *(const float4*)(paras + b * 4);          // wx, wy, bx, by
    const float2 cp = *(const float2*)(cpos + b * 2);           // cx, cy
    const float2 t0 = *(const float2*)(traj + b * 16);          // traj[0]
    const float2 t7 = *(const float2*)(traj + b * 16 + 14);     // traj[7]

    const float wx = pp.x, wy = pp.y, bx = pp.z, by = pp.w;
    const float cx = cp.x, cy = cp.y;

    // moving vector: _obs[-1]-_obs[0] == traj[7]-traj[0] (current_pos cancels)
    const float mvx  = t7.x - t0.x;
    const float mvy  = t7.y - t0.y;
    const float ml2  = mvx * mvx + mvy * mvy;
    const float mlen = (ml2 > 0.0f) ? fsqrt_approx(ml2) : 0.0f;
    const float r    = 2.0f * mlen;       // VISION_RADIUS * moving_length
    const float r2   = r * r;

    // pixel-space bounding box of the disc |map_pos - c| <= r
    const int x0 = max(0, (int)floorf(bx + wx * (cx - r)) - 1);
    const int x1 = min(NPIX - 1, (int)ceilf(bx + wx * (cx + r)) + 1);
    const int y0 = max(0, (int)floorf(by + wy * (cy - r)) - 1);
    const int y1 = min(NPIX - 1, (int)ceilf(by + wy * (cy + r)) + 1);

    const float inv_wx = __fdividef(1.0f, wx);
    const float inv_wy = __fdividef(1.0f, wy);
    const float cxx = -bx * inv_wx - cx;  // dx = px*inv_wx + cxx
    const float cyy = -by * inv_wy - cy;  // dy = py*inv_wy + cyy

    // 4-aligned group tiling. 512 % 4 == 0, so aligned groups never cross the
    // image edge; alignment-padding pixels fail dist<=r exactly.
    const int y0a = y0 & ~3;
    int Gtot = 0, Wg = 1;
    if (x1 >= x0 && y1 >= y0) {
        Wg   = (y1 - y0a + 4) >> 2;                  // exact groups per row
        Gtot = Wg * (x1 - x0 + 1);
    }
    const float invWg = __fdividef(1.0f, (float)Wg);

    const float* __restrict__ sm = seg_maps + (size_t)b * NPIX * NPIX;

    __syncthreads();   // local smin init visible
    // publish init to the cluster; matching wait sits before the cross-CTA
    // commit, so this barrier is hidden behind the whole loop
    asm volatile("barrier.cluster.arrive.aligned;" ::: "memory");

    // group index -> (px, py0): division by Wg via fast reciprocal + fixup
    auto gaddr = [&](int g, int& px, int& py0) {
        int row = __float2int_rz((float)g * invWg);
        int kq  = g - row * Wg;
        if (kq < 0)        { row--; kq += Wg; }
        else if (kq >= Wg) { row++; kq -= Wg; }
        px  = x0 + row;
        py0 = y0a + (kq << 2);
    };

    // per-pixel body (proven R10/R11 fast-math path)
    auto process = [&](int px, int py0, const float4& cur) {
        const float dx  = fmaf((float)px, inv_wx, cxx);
        const float dx2 = dx * dx;
        const float dy0 = fmaf((float)py0, inv_wy, cyy);

        float d2v[4];
        {
            float dyj = dy0;
            #pragma unroll
            for (int j = 0; j < 4; j++) { d2v[j] = fmaf(dyj, dyj, dx2); dyj += inv_wy; }
        }
        const float d2min = fminf(fminf(d2v[0], d2v[1]), fminf(d2v[2], d2v[3]));
        if (d2min > r2) return;

        const float mm[4] = {cur.x, cur.y, cur.z, cur.w};
        float dy = dy0;
        #pragma unroll
        for (int j = 0; j < 4; j++) {
            const float d2 = d2v[j];
            const float m  = mm[j];

            if (d2 <= r2 && m > THRESH) {
                const float dist = fsqrt_approx(d2);   // NaN if d2==0 -> dropped
                if (dist <= r) {
                    const float e = __fdividef(dist + MU_F, m + MU_F);

                    // exact octant of atan2(dx, dy) mod 2pi (select chain)
                    const int bin =
                        (dy > 0.0f) ? ((dx >= 0.0f) ? ((dx <  dy) ? 0 : 1)
                                                    : ((-dx <= dy) ? 7 : 6))
                      : (dy < 0.0f) ? ((dx > 0.0f)  ? ((dx > -dy) ? 2 : 3)
                                                    : ((dx >  dy) ? 4 : 5))
                                    : ((dx > 0.0f) ? 2 : ((dx < 0.0f) ? 6 : 0));

                    // e >= 0: uint order == float order
                    atomicMin(&smin[cpy + bin], __float_as_uint(e));
                }
            }
            dy += inv_wy;
        }
    };

    const int stride = SLICES * CTA;      // 1024: count below is a shift
    const int g0 = s * CTA + tid;

    if (g0 < Gtot) {
        // number of grid-stride iterations for this thread
        const int cnt = (Gtot - g0 + (stride - 1)) >> 10;

        // issue ALL (<=PF) loads back-to-back: one exposed latency round
        int    pxv[PF], pyv[PF];
        float4 v[PF];
        const int cb = min(cnt, PF);
        #pragma unroll
        for (int i = 0; i < PF; i++) {
            if (i < cb) {
                gaddr(g0 + i * stride, pxv[i], pyv[i]);
                v[i] = *(const float4*)(sm + pxv[i] * NPIX + pyv[i]);
            }
        }
        #pragma unroll
        for (int i = 0; i < PF; i++)
            if (i < cb) process(pxv[i], pyv[i], v[i]);

        // fallback for boxes deeper than PF iterations (not hit in practice)
        for (int g = g0 + PF * stride; g < Gtot; g += stride) {
            int px, py0;
            gaddr(g, px, py0);
            const float4 m4 = *(const float4*)(sm + px * NPIX + py0);
            process(px, py0, m4);
        }
    }

    __syncthreads();
    // peer's smin is initialized past this point
    asm volatile("barrier.cluster.wait.aligned;" ::: "memory");

    // fold replicas 1..3 and commit into the leader's replica-0 words
    if (tid < PARTS) {
        unsigned v = min(min(smin[PARTS + tid], smin[2 * PARTS + tid]),
                         smin[3 * PARTS + tid]);
        if (s == 0) {
            if (v != INF_U) atomicMin(&smin[tid], v);
        } else {
            v = min(v, smin[tid]);
            if (v != INF_U) {
                const unsigned laddr =
                    (unsigned)__cvta_generic_to_shared(&smin[tid]);
                unsigned raddr, scratch;
                asm("mapa.shared::cluster.u32 %0, %1, 0;"
                    : "=r"(raddr) : "r"(laddr));
                asm volatile("atom.shared::cluster.min.u32 %0, [%1], %2;"
                             : "=r"(scratch) : "r"(raddr), "r"(v) : "memory");
            }
        }
    }

    // release our commits / acquire the peer's, then leader formats
    asm volatile("barrier.cluster.arrive.aligned;" ::: "memory");
    asm volatile("barrier.cluster.wait.aligned;"   ::: "memory");

    if (s == 0 && tid < MAXPARTS) {
        float v0 = 0.0f, v1 = 0.0f, v2 = 0.0f;
        if (tid < PARTS) {
            const unsigned mb = smin[tid];
            if (mb != INF_U) {
                v0 = mlen;                                            // f_velocity
                v1 = __uint_as_float(mb);                             // f_min_distance
                v2 = 6.283185307179586f * ((float)tid + 0.5f) / 8.0f; // f_direction
            }
        }
        float* ob = out + (size_t)b * MAXPARTS * 3 + tid * 3;
        ob[0] = v0;
        ob[1] = v1;
        ob[2] = v2;
    }
}

extern "C" void kernel_launch(void* const* d_in, const int* in_sizes, int n_in,
                              void* d_out, int out_size) {
    const float* seg_maps = (const float*)d_in[0];  // (128, 512, 512)
    const float* paras    = (const float*)d_in[1];  // (128, 4)
    const float* traj     = (const float*)d_in[2];  // (128, 8, 2)
    const float* cpos     = (const float*)d_in[3];  // (128, 1, 2)
    // d_in[4] = map_pos_pixel: derived analytically from the pixel index, unused
    float* out = (float*)d_out;                     // (128, 16, 3)

    const int B = in_sizes[1] / 4;                  // 128
    dim3 grid(SLICES, B);                           // cluster spans x
    pcl_kernel<<<grid, CTA>>>(seg_maps, paras, traj, cpos, out);
}

// round 15
// speedup vs baseline: 1.0507x; 1.0507x over previous
#include <cuda_runtime.h>
#include <math.h>

#define NPIX 512
#define BMAX 128
#define PARTS 8
#define MAXPARTS 16
#define NCOPY 4
#define SLICES 2
#define CTA 512
#define PF 4                 /* prefetch depth: covers all observed boxes */
#define INF_F 1000000000.0f
#define INF_U 0x4E6E6B28u   /* __float_as_uint(1e9f) */
#define MU_F 1e-8f
#define THRESH 0.05f

// fast approx sqrt: MUFU.RSQ + multiply (d2 == 0 yields NaN -> caller's
// dist<=r test fails, dropping the pixel; exact-center hit is measure-zero)
__device__ __forceinline__ float fsqrt_approx(float x) { return x * rsqrtf(x); }

// Cross-CTA reduction state. Zero-init at module load; self-resetting each
// launch (last CTA per batch clears after formatting). g_min stores ~bits(e),
// atomicMax: for e >= 0 float order == uint order, so max(~bits) == min(e);
// all-zero initial state means "no obstacle".
__device__ unsigned g_min[BMAX * PARTS];
__device__ unsigned g_cnt[BMAX];

// Plain grid (B, SLICES) x 512 threads — no cluster attribute (cluster
// launches showed ~0.3us extra fixed overhead in timed mode). Bbox tiled by
// 4-aligned float4 groups with an exact Wg-wide flattened mapping. ALL of a
// thread's loop iterations (<=PF in every observed case; stride 1024 -> count
// is a shift) issue their LDG.128 back-to-back up front: one exposed memory
// round. MUFU sqrt/div; plain atomicMin into NCOPY replicated shared bin
// words; fold + global atomicMax commit; acq_rel arrival; last CTA per batch
// formats the output and resets the globals for the next graph replay.
__global__ __launch_bounds__(CTA) void pcl_kernel(
    const float* __restrict__ seg_maps,   // (B, N, N)
    const float* __restrict__ paras,      // (B, 4): wx, wy, bx, by
    const float* __restrict__ traj,       // (B, 8, 2)
    const float* __restrict__ cpos,       // (B, 1, 2)
    float* __restrict__ out)              // (B, 16, 3)
{
    const int b   = blockIdx.x;
    const int s   = blockIdx.y;
    const int tid = threadIdx.x;
    const int cpy = (tid & 3) * PARTS;    // replica select

    __shared__ unsigned smin[NCOPY * PARTS];
    if (tid < NCOPY * PARTS) smin[tid] = INF_U;

    // vectorized scalar params: 4 independent loads, one memory round
    const float4 pp = *(const float4*)(paras + b * 4);          // wx, wy, bx, by
    const float2 cp = *(const float2*)(cpos + b * 2);           // cx, cy
    const float2 t0 = *(const float2*)(traj + b * 16);          // traj[0]
    const float2 t7 = *(const float2*)(traj + b * 16 + 14);     // traj[7]

    const float wx = pp.x, wy = pp.y, bx = pp.z, by = pp.w;
    const float cx = cp.x, cy = cp.y;

    // moving vector: _obs[-1]-_obs[0] == traj[7]-traj[0] (current_pos cancels)
    const float mvx  = t7.x - t0.x;
    const float mvy  = t7.y - t0.y;
    const float ml2  = mvx * mvx + mvy * mvy;
    const float mlen = (ml2 > 0.0f) ? fsqrt_approx(ml2) : 0.0f;
    const float r    = 2.0f * mlen;       // VISION_RADIUS * moving_length
    const float r2   = r * r;

    // pixel-space bounding box of the disc |map_pos - c| <= r
    const int x0 = max(0, (int)floorf(bx + wx * (cx - r)) - 1);
    const int x1 = min(NPIX - 1, (int)ceilf(bx + wx * (cx + r)) + 1);
    const int y0 = max(0, (int)floorf(by + wy * (cy - r)) - 1);
    const int y1 = min(NPIX - 1, (int)ceilf(by + wy * (cy + r)) + 1);

    const float inv_wx = __fdividef(1.0f, wx);
    const float inv_wy = __fdividef(1.0f, wy);
    const float cxx = -bx * inv_wx - cx;  // dx = px*inv_wx + cxx
    const float cyy = -by * inv_wy - cy;  // dy = py*inv_wy + cyy

    // 4-aligned group tiling. 512 % 4 == 0, so aligned groups never cross the
    // image edge; alignment-padding pixels fail dist<=r exactly.
    const int y0a = y0 & ~3;
    int Gtot = 0, Wg = 1;
    if (x1 >= x0 && y1 >= y0) {
        Wg   = (y1 - y0a + 4) >> 2;                  // exact groups per row
        Gtot = Wg * (x1 - x0 + 1);
    }
    const float invWg = __fdividef(1.0f, (float)Wg);

    const float* __restrict__ sm = seg_maps + (size_t)b * NPIX * NPIX;

    __syncthreads();   // smin init visible

    // group index -> (px, py0): division by Wg via fast reciprocal + fixup
    auto gaddr = [&](int g, int& px, int& py0) {
        int row = __float2int_rz((float)g * invWg);
        int kq  = g - row * Wg;
        if (kq < 0)        { row--; kq += Wg; }
        else if (kq >= Wg) { row++; kq -= Wg; }
        px  = x0 + row;
        py0 = y0a + (kq << 2);
    };

    // per-pixel body (proven fast-math path)
    auto process = [&](int px, int py0, const float4& cur) {
        const float dx  = fmaf((float)px, inv_wx, cxx);
        const float dx2 = dx * dx;
        const float dy0 = fmaf((float)py0, inv_wy, cyy);

        float d2v[4];
        {
            float dyj = dy0;
            #pragma unroll
            for (int j = 0; j < 4; j++) { d2v[j] = fmaf(dyj, dyj, dx2); dyj += inv_wy; }
        }
        const float d2min = fminf(fminf(d2v[0], d2v[1]), fminf(d2v[2], d2v[3]));
        if (d2min > r2) return;

        const float mm[4] = {cur.x, cur.y, cur.z, cur.w};
        float dy = dy0;
        #pragma unroll
        for (int j = 0; j < 4; j++) {
            const float d2 = d2v[j];
            const float m  = mm[j];

            if (d2 <= r2 && m > THRESH) {
                const float dist = fsqrt_approx(d2);   // NaN if d2==0 -> dropped
                if (dist <= r) {
                    const float e = __fdividef(dist + MU_F, m + MU_F);

                    // exact octant of atan2(dx, dy) mod 2pi (select chain)
                    const int bin =
                        (dy > 0.0f) ? ((dx >= 0.0f) ? ((dx <  dy) ? 0 : 1)
                                                    : ((-dx <= dy) ? 7 : 6))
                      : (dy < 0.0f) ? ((dx > 0.0f)  ? ((dx > -dy) ? 2 : 3)
                                                    : ((dx >  dy) ? 4 : 5))
                                    : ((dx > 0.0f) ? 2 : ((dx < 0.0f) ? 6 : 0));

                    // e >= 0: uint order == float order
                    atomicMin(&smin[cpy + bin], __float_as_uint(e));
                }
            }
            dy += inv_wy;
        }
    };

    const int stride = SLICES * CTA;      // 1024: count below is a shift
    const int g0 = s * CTA + tid;

    if (g0 < Gtot) {
        // number of grid-stride iterations for this thread
        const int cnt = (Gtot - g0 + (stride - 1)) >> 10;

        // issue ALL (<=PF) loads back-to-back: one exposed latency round
        int    pxv[PF], pyv[PF];
        float4 v[PF];
        const int cb = min(cnt, PF);
        #pragma unroll
        for (int i = 0; i < PF; i++) {
            if (i < cb) {
                gaddr(g0 + i * stride, pxv[i], pyv[i]);
                v[i] = *(const float4*)(sm + pxv[i] * NPIX + pyv[i]);
            }
        }
        #pragma unroll
        for (int i = 0; i < PF; i++)
            if (i < cb) process(pxv[i], pyv[i], v[i]);

        // fallback for boxes deeper than PF iterations (not hit in practice)
        for (int g = g0 + PF * stride; g < Gtot; g += stride) {
            int px, py0;
            gaddr(g, px, py0);
            const float4 m4 = *(const float4*)(sm + px * NPIX + py0);
            process(px, py0, m4);
        }
    }

    __syncthreads();

    // fold replicas and commit this CTA's bins to the batch-global mins
    if (tid < PARTS) {
        unsigned v = smin[tid];
        #pragma unroll
        for (int c = 1; c < NCOPY; c++) v = min(v, smin[c * PARTS + tid]);
        if (v != INF_U)
            atomicMax(&g_min[b * PARTS + tid], ~v);
    }
    __syncthreads();

    // arrival with acq_rel ordering: release publishes our g_min commits,
    // acquire (on the last arriver) orders its subsequent g_min reads.
    __shared__ unsigned sprev;
    if (tid == 0) {
        unsigned prev;
        asm volatile("atom.acq_rel.gpu.global.add.u32 %0, [%1], %2;"
                     : "=r"(prev) : "l"(&g_cnt[b]), "r"(1u) : "memory");
        sprev = prev;
    }
    __syncthreads();

    if (sprev == SLICES - 1) {
        if (tid < MAXPARTS) {
            float v0 = 0.0f, v1 = 0.0f, v2 = 0.0f;
            if (tid < PARTS) {
                const unsigned gbits = *(volatile unsigned*)&g_min[b * PARTS + tid];
                if (gbits != 0u) {
                    v0 = mlen;                                            // f_velocity
                    v1 = __uint_as_float(~gbits);                         // f_min_distance
                    v2 = 6.283185307179586f * ((float)tid + 0.5f) / 8.0f; // f_direction
                }
                *(volatile unsigned*)&g_min[b * PARTS + tid] = 0u;        // reset for replay
            }
            if (tid == 0) *(volatile unsigned*)&g_cnt[b] = 0u;            // reset counter
            float* ob = out + (size_t)b * MAXPARTS * 3 + tid * 3;
            ob[0] = v0;
            ob[1] = v1;
            ob[2] = v2;
        }
    }
}

extern "C" void kernel_launch(void* const* d_in, const int* in_sizes, int n_in,
                              void* d_out, int out_size) {
    const float* seg_maps = (const float*)d_in[0];  // (128, 512, 512)
    const float* paras    = (const float*)d_in[1];  // (128, 4)
    const float* traj     = (const float*)d_in[2];  // (128, 8, 2)
    const float* cpos     = (const float*)d_in[3];  // (128, 1, 2)
    // d_in[4] = map_pos_pixel: derived analytically from the pixel index, unused
    float* out = (float*)d_out;                     // (128, 16, 3)

    const int B = in_sizes[1] / 4;                  // 128
    dim3 grid(B, SLICES);
    pcl_kernel<<<grid, CTA>>>(seg_maps, paras, traj, cpos, out);
}